// round 2
// baseline (speedup 1.0000x reference)
#include <cuda_runtime.h>

#define N_CODES 16384
#define DIM     512
#define BM      64
#define BN      128
#define BK      32
#define THREADS 256
#define DIST_THRESHOLD 900.0f

// scratch: code squared norms (no cudaMalloc allowed)
__device__ float g_c2[N_CODES];

// ---------------------------------------------------------------------------
// Kernel 1: code norms. One warp per code row (512 floats = 16/lane as float4).
// ---------------------------------------------------------------------------
__global__ __launch_bounds__(256) void c2_kernel(const float* __restrict__ codes) {
    int warp = (blockIdx.x * blockDim.x + threadIdx.x) >> 5;
    int lane = threadIdx.x & 31;
    if (warp >= N_CODES) return;
    const float4* row = (const float4*)(codes + (size_t)warp * DIM);
    float s = 0.0f;
#pragma unroll
    for (int i = 0; i < 4; i++) {
        float4 v = row[lane + 32 * i];
        s = fmaf(v.x, v.x, s);
        s = fmaf(v.y, v.y, s);
        s = fmaf(v.z, v.z, s);
        s = fmaf(v.w, v.w, s);
    }
#pragma unroll
    for (int o = 16; o > 0; o >>= 1)
        s += __shfl_xor_sync(0xffffffffu, s, o);
    if (lane == 0) g_c2[warp] = s;
}

// ---------------------------------------------------------------------------
// Kernel 2: fused distance GEMM + running argmin.
// CTA: BM=64 tokens, streams all codes in BN=128 tiles, K tiled by 32.
// Thread (tx,ty), tx=0..15, ty=0..15: 4 rows (ty*4..) x 8 cols (tx*8..).
// ---------------------------------------------------------------------------
__global__ __launch_bounds__(THREADS) void nn_kernel(
    const float* __restrict__ x,
    const float* __restrict__ codes,
    float* __restrict__ out)
{
    // padded so the hot-loop float4 LDS are conflict-free (stores pay, once)
    __shared__ __align__(16) float As[BK][BM + 4];   // [k][m]
    __shared__ __align__(16) float Bs[BK][BN + 4];   // [k][n]
    __shared__ float x2s[BM];
    __shared__ float red_val[BM][16];
    __shared__ int   red_idx[BM][16];

    const int tid = threadIdx.x;
    const int tx = tid & 15;        // column group
    const int ty = tid >> 4;        // row group
    const int row0 = blockIdx.x * BM;

    // ---- per-token ||x||^2 : 4 threads per token, 128 floats each ----
    {
        int m = tid >> 2;           // 0..63
        int p = tid & 3;
        const float4* xr = (const float4*)(x + (size_t)(row0 + m) * DIM + p * 128);
        float s = 0.0f;
#pragma unroll 8
        for (int i = 0; i < 32; i++) {
            float4 v = xr[i];
            s = fmaf(v.x, v.x, s);
            s = fmaf(v.y, v.y, s);
            s = fmaf(v.z, v.z, s);
            s = fmaf(v.w, v.w, s);
        }
        s += __shfl_xor_sync(0xffffffffu, s, 1);
        s += __shfl_xor_sync(0xffffffffu, s, 2);
        if (p == 0) x2s[m] = s;
    }

    float minv[4];
    int   mini[4];
#pragma unroll
    for (int i = 0; i < 4; i++) { minv[i] = 3.4e38f; mini[i] = 0; }

    for (int nt = 0; nt < N_CODES; nt += BN) {
        float acc[4][8];
#pragma unroll
        for (int i = 0; i < 4; i++)
#pragma unroll
            for (int j = 0; j < 8; j++) acc[i][j] = 0.0f;

        for (int kt = 0; kt < DIM; kt += BK) {
            __syncthreads();
            // load A tile: 64x32 = 512 float4, 2 per thread
            {
                int f = tid;
#pragma unroll
                for (int r = 0; r < 2; r++, f += THREADS) {
                    int m  = f >> 3;
                    int k4 = (f & 7) << 2;
                    float4 v = *(const float4*)(x + (size_t)(row0 + m) * DIM + kt + k4);
                    As[k4 + 0][m] = v.x;
                    As[k4 + 1][m] = v.y;
                    As[k4 + 2][m] = v.z;
                    As[k4 + 3][m] = v.w;
                }
            }
            // load B tile: 128x32 = 1024 float4, 4 per thread
            {
                int f = tid;
#pragma unroll
                for (int r = 0; r < 4; r++, f += THREADS) {
                    int n  = f >> 3;
                    int k4 = (f & 7) << 2;
                    float4 v = *(const float4*)(codes + (size_t)(nt + n) * DIM + kt + k4);
                    Bs[k4 + 0][n] = v.x;
                    Bs[k4 + 1][n] = v.y;
                    Bs[k4 + 2][n] = v.z;
                    Bs[k4 + 3][n] = v.w;
                }
            }
            __syncthreads();

#pragma unroll
            for (int k = 0; k < BK; k++) {
                float4 a  = *(const float4*)&As[k][ty << 2];
                float4 b0 = *(const float4*)&Bs[k][tx << 3];
                float4 b1 = *(const float4*)&Bs[k][(tx << 3) + 4];
                float af[4] = {a.x, a.y, a.z, a.w};
                float bf[8] = {b0.x, b0.y, b0.z, b0.w, b1.x, b1.y, b1.z, b1.w};
#pragma unroll
                for (int i = 0; i < 4; i++)
#pragma unroll
                    for (int j = 0; j < 8; j++)
                        acc[i][j] = fmaf(af[i], bf[j], acc[i][j]);
            }
        }

        // epilogue: val = c2[n] - 2*dot ; running (min, argmin); n ascending
#pragma unroll
        for (int j = 0; j < 8; j++) {
            int n = nt + (tx << 3) + j;
            float c2 = g_c2[n];
#pragma unroll
            for (int i = 0; i < 4; i++) {
                float v = fmaf(-2.0f, acc[i][j], c2);
                if (v < minv[i]) { minv[i] = v; mini[i] = n; }
            }
        }
    }

    __syncthreads();
#pragma unroll
    for (int i = 0; i < 4; i++) {
        red_val[(ty << 2) + i][tx] = minv[i];
        red_idx[(ty << 2) + i][tx] = mini[i];
    }
    __syncthreads();

    if (tid < BM) {
        int m = tid;
        float bv = red_val[m][0];
        int   bi = red_idx[m][0];
#pragma unroll
        for (int t = 1; t < 16; t++) {
            float v = red_val[m][t];
            int   id = red_idx[m][t];
            if (v < bv || (v == bv && id < bi)) { bv = v; bi = id; }
        }
        float dist = x2s[m] + bv;            // clamp(.,0) irrelevant: 900 > 0
        // output dtype is float32 (NaN evidence from R1): write ids as floats
        out[row0 + m] = (dist <= DIST_THRESHOLD) ? (float)bi : -1.0f;
    }
}

// ---------------------------------------------------------------------------
extern "C" void kernel_launch(void* const* d_in, const int* in_sizes, int n_in,
                              void* d_out, int out_size) {
    const float* x     = (const float*)d_in[0];  // [8192, 512]
    const float* codes = (const float*)d_in[1];  // [16384, 512]
    float* out = (float*)d_out;                  // [8192] float32 ids

    int n_tokens = out_size;                     // 8192

    c2_kernel<<<(N_CODES * 32) / 256, 256>>>(codes);
    nn_kernel<<<n_tokens / BM, THREADS>>>(x, codes, out);
}

// round 3
// speedup vs baseline: 1.0000x; 1.0000x over previous
#include <cuda_runtime.h>

#define N_CODES 16384
#define DIM     512
#define BM      64
#define BN      128
#define BK      32
#define THREADS 256
#define DIST_THRESHOLD 900.0f

// scratch: code squared norms (no cudaMalloc allowed)
__device__ float g_c2[N_CODES];

// ---------------------------------------------------------------------------
// Kernel 1: code norms. One warp per code row (512 floats = 16/lane as float4).
// ---------------------------------------------------------------------------
__global__ __launch_bounds__(256) void c2_kernel(const float* __restrict__ codes) {
    int warp = (blockIdx.x * blockDim.x + threadIdx.x) >> 5;
    int lane = threadIdx.x & 31;
    if (warp >= N_CODES) return;
    const float4* row = (const float4*)(codes + (size_t)warp * DIM);
    float s = 0.0f;
#pragma unroll
    for (int i = 0; i < 4; i++) {
        float4 v = row[lane + 32 * i];
        s = fmaf(v.x, v.x, s);
        s = fmaf(v.y, v.y, s);
        s = fmaf(v.z, v.z, s);
        s = fmaf(v.w, v.w, s);
    }
#pragma unroll
    for (int o = 16; o > 0; o >>= 1)
        s += __shfl_xor_sync(0xffffffffu, s, o);
    if (lane == 0) g_c2[warp] = s;
}

// ---------------------------------------------------------------------------
// Kernel 2: fused distance GEMM + running argmin.
// CTA: BM=64 tokens, streams all codes in BN=128 tiles, K tiled by 32.
// Thread (tx,ty), tx=0..15, ty=0..15: 4 rows (ty*4..) x 8 cols (tx*8..).
// ---------------------------------------------------------------------------
__global__ __launch_bounds__(THREADS) void nn_kernel(
    const float* __restrict__ x,
    const float* __restrict__ codes,
    float* __restrict__ out)
{
    // padded so the hot-loop float4 LDS are conflict-free (stores pay, once)
    __shared__ __align__(16) float As[BK][BM + 4];   // [k][m]
    __shared__ __align__(16) float Bs[BK][BN + 4];   // [k][n]
    __shared__ float x2s[BM];
    __shared__ float red_val[BM][16];
    __shared__ int   red_idx[BM][16];

    const int tid = threadIdx.x;
    const int tx = tid & 15;        // column group
    const int ty = tid >> 4;        // row group
    const int row0 = blockIdx.x * BM;

    // ---- per-token ||x||^2 : 4 threads per token, 128 floats each ----
    {
        int m = tid >> 2;           // 0..63
        int p = tid & 3;
        const float4* xr = (const float4*)(x + (size_t)(row0 + m) * DIM + p * 128);
        float s = 0.0f;
#pragma unroll 8
        for (int i = 0; i < 32; i++) {
            float4 v = xr[i];
            s = fmaf(v.x, v.x, s);
            s = fmaf(v.y, v.y, s);
            s = fmaf(v.z, v.z, s);
            s = fmaf(v.w, v.w, s);
        }
        s += __shfl_xor_sync(0xffffffffu, s, 1);
        s += __shfl_xor_sync(0xffffffffu, s, 2);
        if (p == 0) x2s[m] = s;
    }

    float minv[4];
    int   mini[4];
#pragma unroll
    for (int i = 0; i < 4; i++) { minv[i] = 3.4e38f; mini[i] = 0; }

    for (int nt = 0; nt < N_CODES; nt += BN) {
        float acc[4][8];
#pragma unroll
        for (int i = 0; i < 4; i++)
#pragma unroll
            for (int j = 0; j < 8; j++) acc[i][j] = 0.0f;

        for (int kt = 0; kt < DIM; kt += BK) {
            __syncthreads();
            // load A tile: 64x32 = 512 float4, 2 per thread
            {
                int f = tid;
#pragma unroll
                for (int r = 0; r < 2; r++, f += THREADS) {
                    int m  = f >> 3;
                    int k4 = (f & 7) << 2;
                    float4 v = *(const float4*)(x + (size_t)(row0 + m) * DIM + kt + k4);
                    As[k4 + 0][m] = v.x;
                    As[k4 + 1][m] = v.y;
                    As[k4 + 2][m] = v.z;
                    As[k4 + 3][m] = v.w;
                }
            }
            // load B tile: 128x32 = 1024 float4, 4 per thread
            {
                int f = tid;
#pragma unroll
                for (int r = 0; r < 4; r++, f += THREADS) {
                    int n  = f >> 3;
                    int k4 = (f & 7) << 2;
                    float4 v = *(const float4*)(codes + (size_t)(nt + n) * DIM + kt + k4);
                    Bs[k4 + 0][n] = v.x;
                    Bs[k4 + 1][n] = v.y;
                    Bs[k4 + 2][n] = v.z;
                    Bs[k4 + 3][n] = v.w;
                }
            }
            __syncthreads();

#pragma unroll
            for (int k = 0; k < BK; k++) {
                float4 a  = *(const float4*)&As[k][ty << 2];
                float4 b0 = *(const float4*)&Bs[k][tx << 3];
                float4 b1 = *(const float4*)&Bs[k][(tx << 3) + 4];
                float af[4] = {a.x, a.y, a.z, a.w};
                float bf[8] = {b0.x, b0.y, b0.z, b0.w, b1.x, b1.y, b1.z, b1.w};
#pragma unroll
                for (int i = 0; i < 4; i++)
#pragma unroll
                    for (int j = 0; j < 8; j++)
                        acc[i][j] = fmaf(af[i], bf[j], acc[i][j]);
            }
        }

        // epilogue: val = c2[n] - 2*dot ; running (min, argmin); n ascending
#pragma unroll
        for (int j = 0; j < 8; j++) {
            int n = nt + (tx << 3) + j;
            float c2 = g_c2[n];
#pragma unroll
            for (int i = 0; i < 4; i++) {
                float v = fmaf(-2.0f, acc[i][j], c2);
                if (v < minv[i]) { minv[i] = v; mini[i] = n; }
            }
        }
    }

    __syncthreads();
#pragma unroll
    for (int i = 0; i < 4; i++) {
        red_val[(ty << 2) + i][tx] = minv[i];
        red_idx[(ty << 2) + i][tx] = mini[i];
    }
    __syncthreads();

    if (tid < BM) {
        int m = tid;
        float bv = red_val[m][0];
        int   bi = red_idx[m][0];
#pragma unroll
        for (int t = 1; t < 16; t++) {
            float v = red_val[m][t];
            int   id = red_idx[m][t];
            if (v < bv || (v == bv && id < bi)) { bv = v; bi = id; }
        }
        float dist = x2s[m] + bv;            // clamp(.,0) irrelevant: 900 > 0
        // output dtype is float32 (NaN evidence from R1): write ids as floats
        out[row0 + m] = (dist <= DIST_THRESHOLD) ? (float)bi : -1.0f;
    }
}

// ---------------------------------------------------------------------------
extern "C" void kernel_launch(void* const* d_in, const int* in_sizes, int n_in,
                              void* d_out, int out_size) {
    const float* x     = (const float*)d_in[0];  // [8192, 512]
    const float* codes = (const float*)d_in[1];  // [16384, 512]
    float* out = (float*)d_out;                  // [8192] float32 ids

    int n_tokens = out_size;                     // 8192

    c2_kernel<<<(N_CODES * 32) / 256, 256>>>(codes);
    nn_kernel<<<n_tokens / BM, THREADS>>>(x, codes, out);
}

// round 5
// speedup vs baseline: 4.8519x; 4.8519x over previous
#include <cuda_runtime.h>
#include <cuda_fp16.h>
#include <cstdint>

#define N_CODES 16384
#define N_TOK   8192
#define DIM     512
#define KV      1536              // [xh | xl | xh] . [ch | ch | cl]
#define THRESH  900.0f
#define BM      128
#define BN      256
#define BKH     64                // 64 halves = 128 bytes per row
#define NKC     24                // 1536/64
#define NTILE   32                // 8192/256
#define NG      (NTILE*NKC)
#define STG     49152u            // A 16KB + B 32KB
#define SMEM_DYN (3u*STG)
#define SWZ(o) ((o) ^ (((o)>>3)&0x70))

__device__ __align__(128) __half g_A[(size_t)N_TOK*KV];
__device__ __align__(128) __half g_B[(size_t)N_CODES*KV];
__device__ __align__(16) float g_c2[N_CODES];
__device__ __align__(16) float g_x2[N_TOK];
__device__ float g_pacc[2*N_TOK];
__device__ int   g_pidx[2*N_TOK];

__device__ __forceinline__ uint32_t s2u(const void* p){
    uint32_t a;
    asm("{ .reg .u64 t; cvta.to.shared.u64 t, %1; cvt.u32.u64 %0, t; }" : "=r"(a) : "l"(p));
    return a;
}
#define CPASYNC16(d,s) asm volatile("cp.async.cg.shared.global [%0], [%1], 16;" :: "r"(d),"l"(s) : "memory")
#define LDSM4(r0,r1,r2,r3,a) asm volatile("ldmatrix.sync.aligned.m8n8.x4.shared.b16 {%0,%1,%2,%3}, [%4];" \
    : "=r"(r0),"=r"(r1),"=r"(r2),"=r"(r3) : "r"(a))
#define LDSM2(r0,r1,a) asm volatile("ldmatrix.sync.aligned.m8n8.x2.shared.b16 {%0,%1}, [%2];" \
    : "=r"(r0),"=r"(r1) : "r"(a))
#define MMA(c,a,b0,b1) asm volatile( \
    "mma.sync.aligned.m16n8k16.row.col.f32.f16.f16.f32 {%0,%1,%2,%3},{%4,%5,%6,%7},{%8,%9},{%0,%1,%2,%3};" \
    : "+f"((c)[0]),"+f"((c)[1]),"+f"((c)[2]),"+f"((c)[3]) \
    : "r"((a)[0]),"r"((a)[1]),"r"((a)[2]),"r"((a)[3]),"r"(b0),"r"(b1))

// ---- prep: fp32 -> fp16 hi/lo split into K-concatenated A'/B' + norms ------
__global__ __launch_bounds__(256) void prep(const float* __restrict__ x,
                                            const float* __restrict__ codes){
    int w=(blockIdx.x*256+threadIdx.x)>>5, lane=threadIdx.x&31;
    if (w>=N_TOK+N_CODES) return;
    bool isx = w<N_TOK;
    int row = isx ? w : w-N_TOK;
    const float* src = isx ? x+(size_t)row*DIM : codes+(size_t)row*DIM;
    __half* d = isx ? g_A+(size_t)row*KV : g_B+(size_t)row*KV;
    float s=0.f;
#pragma unroll
    for (int i=0;i<4;i++){
        float4 v = ((const float4*)src)[lane+32*i];
        int c=(lane+32*i)*4;
        float vv[4]={v.x,v.y,v.z,v.w};
#pragma unroll
        for (int u=0;u<4;u++){
            float f=vv[u];
            __half h=__float2half_rn(f);
            __half l=__float2half_rn(f-__half2float(h));
            if (isx){ d[c+u]=h; d[512+c+u]=l; d[1024+c+u]=h; }
            else    { d[c+u]=h; d[512+c+u]=h; d[1024+c+u]=l; }
            s=fmaf(f,f,s);
        }
    }
#pragma unroll
    for (int o=16;o>0;o>>=1) s += __shfl_xor_sync(0xffffffffu,s,o);
    if (lane==0){ if (isx) g_x2[row]=s; else g_c2[row]=s; }
}

// ---- main GEMM + fused argmin ---------------------------------------------
__device__ __forceinline__ void issue_chunk(uint32_t sd,int tid,int row0,int nbase,int g){
    int it=g/NKC, kc=g%NKC;
    uint32_t st = sd + (uint32_t)(g%3)*STG;
    const __half* pa = g_A + (size_t)row0*KV + kc*BKH;
    const __half* pb = g_B + (size_t)(nbase+it*BN)*KV + kc*BKH;
#pragma unroll
    for (int i=0;i<2;i++){
        int id=tid+i*512, r=id>>3, c=id&7;
        CPASYNC16(st + SWZ((uint32_t)(r*128+c*16)), pa + (size_t)r*KV + c*8);
    }
#pragma unroll
    for (int i=0;i<4;i++){
        int id=tid+i*512, r=id>>3, c=id&7;
        CPASYNC16(st + 16384u + SWZ((uint32_t)(r*128+c*16)), pb + (size_t)r*KV + c*8);
    }
    asm volatile("cp.async.commit_group;" ::: "memory");
}

__global__ __launch_bounds__(512,1) void nn_hmma(){
    extern __shared__ __align__(1024) char dsm[];
    __shared__ __align__(16) float c2s[BN];
    __shared__ float rv[BM][4];
    __shared__ int   ri[BM][4];
    const uint32_t sd = s2u(dsm);
    const int tid=threadIdx.x, l=tid&31, wid=tid>>5;
    const int wr=wid>>2, wc=wid&3;          // warp 32x64 tile at (wr*32, wc*64)
    const int row0=blockIdx.x*BM;
    const int nbase=blockIdx.y*(N_CODES/2);

    float acc[2][8][4];
#pragma unroll
    for (int a=0;a<2;a++)
#pragma unroll
        for (int b=0;b<8;b++)
#pragma unroll
            for (int c=0;c<4;c++) acc[a][b][c]=0.f;
    float minv[4]; int mini[4];
#pragma unroll
    for (int i=0;i<4;i++){ minv[i]=3.4e38f; mini[i]=0; }

    issue_chunk(sd,tid,row0,nbase,0);
    issue_chunk(sd,tid,row0,nbase,1);

    for (int g=0; g<NG; g++){
        const int it=g/NKC, kc=g%NKC;
        if (g==NG-1) asm volatile("cp.async.wait_group 0;" ::: "memory");
        else         asm volatile("cp.async.wait_group 1;" ::: "memory");
        __syncthreads();
        if (g+2<NG) issue_chunk(sd,tid,row0,nbase,g+2);
        if (kc==0 && tid<64)
            *(float4*)(c2s+tid*4) = *(const float4*)(g_c2 + nbase + it*BN + tid*4);

        const uint32_t stA = sd + (uint32_t)(g%3)*STG;
        const uint32_t stB = stA + 16384u;
#pragma unroll
        for (int kk=0;kk<4;kk++){
            uint32_t a[2][4];
#pragma unroll
            for (int mt=0;mt<2;mt++){
                uint32_t row=(uint32_t)(wr*32+mt*16+(l&15));
                uint32_t col=(uint32_t)(kk*32+((l>>4)<<4));
                uint32_t ad=stA+SWZ(row*128u+col);
                LDSM4(a[mt][0],a[mt][1],a[mt][2],a[mt][3],ad);
            }
#pragma unroll
            for (int nt=0;nt<8;nt++){
                uint32_t brow=(uint32_t)(wc*64+nt*8+(l&7));
                uint32_t bcol=(uint32_t)(kk*32+(((l>>3)&1)<<4));
                uint32_t bd=stB+SWZ(brow*128u+bcol);
                uint32_t b0,b1;
                LDSM2(b0,b1,bd);
                MMA(acc[0][nt],a[0],b0,b1);
                MMA(acc[1][nt],a[1],b0,b1);
            }
        }
        if (kc==NKC-1){
            int tilen = nbase + it*BN;
#pragma unroll
            for (int mt=0;mt<2;mt++)
#pragma unroll
                for (int nt=0;nt<8;nt++){
                    int nl = wc*64 + nt*8 + (l&3)*2;
                    float c2v0=c2s[nl], c2v1=c2s[nl+1];
                    float* c = acc[mt][nt];
                    float v0=fmaf(-2.f,c[0],c2v0), v1=fmaf(-2.f,c[1],c2v1);
                    float v2=fmaf(-2.f,c[2],c2v0), v3=fmaf(-2.f,c[3],c2v1);
                    int m0=mt*2, m1=mt*2+1, n=tilen+nl;
                    if (v0<minv[m0]){ minv[m0]=v0; mini[m0]=n; }
                    if (v1<minv[m0]){ minv[m0]=v1; mini[m0]=n+1; }
                    if (v2<minv[m1]){ minv[m1]=v2; mini[m1]=n; }
                    if (v3<minv[m1]){ minv[m1]=v3; mini[m1]=n+1; }
                    c[0]=c[1]=c[2]=c[3]=0.f;
                }
        }
    }
    // reduce across the 4 lanes sharing each output row (l&3)
#pragma unroll
    for (int q=1;q<4;q<<=1)
#pragma unroll
        for (int i=0;i<4;i++){
            float ov=__shfl_xor_sync(0xffffffffu,minv[i],q);
            int   oi=__shfl_xor_sync(0xffffffffu,mini[i],q);
            if (ov<minv[i] || (ov==minv[i] && oi<mini[i])){ minv[i]=ov; mini[i]=oi; }
        }
    if ((l&3)==0){
        int gq=l>>2;
#pragma unroll
        for (int mt=0;mt<2;mt++){
            int r0=wr*32+mt*16+gq;
            rv[r0][wc]=minv[mt*2];   ri[r0][wc]=mini[mt*2];
            rv[r0+8][wc]=minv[mt*2+1]; ri[r0+8][wc]=mini[mt*2+1];
        }
    }
    __syncthreads();
    if (tid<BM){
        float bv=rv[tid][0]; int bi=ri[tid][0];
#pragma unroll
        for (int c=1;c<4;c++){
            float v=rv[tid][c]; int i=ri[tid][c];
            if (v<bv || (v==bv && i<bi)){ bv=v; bi=i; }
        }
        g_pacc[blockIdx.y*N_TOK+row0+tid]=bv;
        g_pidx[blockIdx.y*N_TOK+row0+tid]=bi;
    }
}

__global__ __launch_bounds__(256) void fin(float* __restrict__ out){
    int t=blockIdx.x*256+threadIdx.x;
    if (t>=N_TOK) return;
    float v0=g_pacc[t], v1=g_pacc[N_TOK+t];
    int   i0=g_pidx[t], i1=g_pidx[N_TOK+t];
    float bv=v0; int bi=i0;
    if (v1<bv || (v1==bv && i1<bi)){ bv=v1; bi=i1; }
    out[t] = (g_x2[t]+bv <= THRESH) ? (float)bi : -1.0f;
}

extern "C" void kernel_launch(void* const* d_in, const int* in_sizes, int n_in,
                              void* d_out, int out_size){
    const float* x=(const float*)d_in[0];
    const float* codes=(const float*)d_in[1];
    float* out=(float*)d_out;
    cudaFuncSetAttribute(nn_hmma, cudaFuncAttributeMaxDynamicSharedMemorySize, SMEM_DYN);
    prep<<<(N_TOK+N_CODES)/8, 256>>>(x, codes);
    dim3 grid(64,2);
    nn_hmma<<<grid, 512, SMEM_DYN>>>();
    fin<<<N_TOK/256, 256>>>(out);
}

// round 6
// speedup vs baseline: 9.7026x; 1.9997x over previous
#include <cuda_runtime.h>
#include <cuda_fp16.h>
#include <cstdint>

#define N_CODES 16384
#define N_TOK   8192
#define DIM     512
#define THRESH  900.0f
#define MARGIN  8.0f
#define BM      128
#define BN      256
#define NKC     8                 // 512/64
#define NTILE   32                // 8192/256
#define NG      (NTILE*NKC)
#define STG     49152u            // A 16KB + B 32KB
#define SMEM_DYN (3u*STG)
#define SWZ(o) ((o) ^ (((o)>>3)&0x70))

__device__ __align__(128) __half g_A[(size_t)N_TOK*DIM];     // x hi
__device__ __align__(128) __half g_B[(size_t)N_CODES*DIM];   // codes hi
__device__ __align__(16)  __half g_dist[(size_t)N_TOK*N_CODES];
__device__ __align__(16) float g_c2[N_CODES];
__device__ __align__(16) float g_x2[N_TOK];
__device__ float g_pacc[2*N_TOK];

__device__ __forceinline__ uint32_t s2u(const void* p){
    uint32_t a;
    asm("{ .reg .u64 t; cvta.to.shared.u64 t, %1; cvt.u32.u64 %0, t; }" : "=r"(a) : "l"(p));
    return a;
}
#define CPASYNC16(d,s) asm volatile("cp.async.cg.shared.global [%0], [%1], 16;" :: "r"(d),"l"(s) : "memory")
#define LDSM4(r0,r1,r2,r3,a) asm volatile("ldmatrix.sync.aligned.m8n8.x4.shared.b16 {%0,%1,%2,%3}, [%4];" \
    : "=r"(r0),"=r"(r1),"=r"(r2),"=r"(r3) : "r"(a))
#define LDSM2(r0,r1,a) asm volatile("ldmatrix.sync.aligned.m8n8.x2.shared.b16 {%0,%1}, [%2];" \
    : "=r"(r0),"=r"(r1) : "r"(a))
#define MMA(c,a,b0,b1) asm volatile( \
    "mma.sync.aligned.m16n8k16.row.col.f32.f16.f16.f32 {%0,%1,%2,%3},{%4,%5,%6,%7},{%8,%9},{%0,%1,%2,%3};" \
    : "+f"((c)[0]),"+f"((c)[1]),"+f"((c)[2]),"+f"((c)[3]) \
    : "r"((a)[0]),"r"((a)[1]),"r"((a)[2]),"r"((a)[3]),"r"(b0),"r"(b1))

// ---- prep: fp32 -> fp16 (hi only) + squared norms. one warp per row. ------
__global__ __launch_bounds__(256) void prep(const float* __restrict__ x,
                                            const float* __restrict__ codes){
    int w=(blockIdx.x*256+threadIdx.x)>>5, lane=threadIdx.x&31;
    if (w>=N_TOK+N_CODES) return;
    bool isx = w<N_TOK;
    int row = isx ? w : w-N_TOK;
    const float* src = isx ? x+(size_t)row*DIM : codes+(size_t)row*DIM;
    __half* d = isx ? g_A+(size_t)row*DIM : g_B+(size_t)row*DIM;
    float s=0.f;
#pragma unroll
    for (int i=0;i<4;i++){
        float4 v = ((const float4*)src)[lane+32*i];
        int c=(lane+32*i)*4;
        float vv[4]={v.x,v.y,v.z,v.w};
        __half2 h0=__floats2half2_rn(vv[0],vv[1]);
        __half2 h1=__floats2half2_rn(vv[2],vv[3]);
        *(__half2*)(d+c)=h0; *(__half2*)(d+c+2)=h1;
#pragma unroll
        for (int u=0;u<4;u++) s=fmaf(vv[u],vv[u],s);
    }
#pragma unroll
    for (int o=16;o>0;o>>=1) s += __shfl_xor_sync(0xffffffffu,s,o);
    if (lane==0){ if (isx) g_x2[row]=s; else g_c2[row]=s; }
}

// ---- approx GEMM + fused min + fp16 distance store ------------------------
__device__ __forceinline__ void issue_chunk(uint32_t sd,int tid,int row0,int nbase,int g){
    int it=g/NKC, kc=g%NKC;
    uint32_t st = sd + (uint32_t)(g%3)*STG;
    const __half* pa = g_A + (size_t)row0*DIM + kc*64;
    const __half* pb = g_B + (size_t)(nbase+it*BN)*DIM + kc*64;
#pragma unroll
    for (int i=0;i<2;i++){
        int id=tid+i*512, r=id>>3, c=id&7;
        CPASYNC16(st + SWZ((uint32_t)(r*128+c*16)), pa + (size_t)r*DIM + c*8);
    }
#pragma unroll
    for (int i=0;i<4;i++){
        int id=tid+i*512, r=id>>3, c=id&7;
        CPASYNC16(st + 16384u + SWZ((uint32_t)(r*128+c*16)), pb + (size_t)r*DIM + c*8);
    }
    asm volatile("cp.async.commit_group;" ::: "memory");
}

__global__ __launch_bounds__(512,1) void nn_hmma(){
    extern __shared__ __align__(1024) char dsm[];
    __shared__ __align__(16) float c2s[BN];
    __shared__ float rv[BM][4];
    const uint32_t sd = s2u(dsm);
    const int tid=threadIdx.x, l=tid&31, wid=tid>>5;
    const int wr=wid>>2, wc=wid&3;          // warp 32x64 tile at (wr*32, wc*64)
    const int row0=blockIdx.x*BM;
    const int nbase=blockIdx.y*(N_CODES/2);

    float acc[2][8][4];
#pragma unroll
    for (int a=0;a<2;a++)
#pragma unroll
        for (int b=0;b<8;b++)
#pragma unroll
            for (int c=0;c<4;c++) acc[a][b][c]=0.f;
    float minv[4];
#pragma unroll
    for (int i=0;i<4;i++) minv[i]=3.4e38f;

    issue_chunk(sd,tid,row0,nbase,0);
    issue_chunk(sd,tid,row0,nbase,1);

    for (int g=0; g<NG; g++){
        const int it=g/NKC, kc=g%NKC;
        if (g==NG-1) asm volatile("cp.async.wait_group 0;" ::: "memory");
        else         asm volatile("cp.async.wait_group 1;" ::: "memory");
        __syncthreads();
        if (g+2<NG) issue_chunk(sd,tid,row0,nbase,g+2);
        if (kc==0 && tid<64)
            *(float4*)(c2s+tid*4) = *(const float4*)(g_c2 + nbase + it*BN + tid*4);

        const uint32_t stA = sd + (uint32_t)(g%3)*STG;
        const uint32_t stB = stA + 16384u;
#pragma unroll
        for (int kk=0;kk<4;kk++){
            uint32_t a[2][4];
#pragma unroll
            for (int mt=0;mt<2;mt++){
                uint32_t row=(uint32_t)(wr*32+mt*16+(l&15));
                uint32_t col=(uint32_t)(kk*32+((l>>4)<<4));
                LDSM4(a[mt][0],a[mt][1],a[mt][2],a[mt][3], stA+SWZ(row*128u+col));
            }
#pragma unroll
            for (int nt=0;nt<8;nt++){
                uint32_t brow=(uint32_t)(wc*64+nt*8+(l&7));
                uint32_t bcol=(uint32_t)(kk*32+(((l>>3)&1)<<4));
                uint32_t b0,b1;
                LDSM2(b0,b1, stB+SWZ(brow*128u+bcol));
                MMA(acc[0][nt],a[0],b0,b1);
                MMA(acc[1][nt],a[1],b0,b1);
            }
        }
        if (kc==NKC-1){
            const int tilen = nbase + it*BN;
#pragma unroll
            for (int mt=0;mt<2;mt++){
                const int m0 = row0 + wr*32 + mt*16 + (l>>2);
#pragma unroll
                for (int nt=0;nt<8;nt++){
                    int nl = wc*64 + nt*8 + (l&3)*2;
                    float c2v0=c2s[nl], c2v1=c2s[nl+1];
                    float* c = acc[mt][nt];
                    float v0=fmaf(-2.f,c[0],c2v0), v1=fmaf(-2.f,c[1],c2v1);
                    float v2=fmaf(-2.f,c[2],c2v0), v3=fmaf(-2.f,c[3],c2v1);
                    int i0=mt*2, i1=mt*2+1;
                    minv[i0]=fminf(minv[i0],fminf(v0,v1));
                    minv[i1]=fminf(minv[i1],fminf(v2,v3));
                    *(__half2*)(g_dist + (size_t)m0*N_CODES + tilen + nl)     = __floats2half2_rn(v0,v1);
                    *(__half2*)(g_dist + (size_t)(m0+8)*N_CODES + tilen + nl) = __floats2half2_rn(v2,v3);
                    c[0]=c[1]=c[2]=c[3]=0.f;
                }
            }
        }
    }
#pragma unroll
    for (int q=1;q<4;q<<=1)
#pragma unroll
        for (int i=0;i<4;i++)
            minv[i]=fminf(minv[i], __shfl_xor_sync(0xffffffffu,minv[i],q));
    if ((l&3)==0){
        int gq=l>>2;
#pragma unroll
        for (int mt=0;mt<2;mt++){
            int r0=wr*32+mt*16+gq;
            rv[r0][wc]=minv[mt*2];
            rv[r0+8][wc]=minv[mt*2+1];
        }
    }
    __syncthreads();
    if (tid<BM){
        float bv=fminf(fminf(rv[tid][0],rv[tid][1]),fminf(rv[tid][2],rv[tid][3]));
        g_pacc[blockIdx.y*N_TOK+row0+tid]=bv;
    }
}

// ---- refine: scan fp16 row, exact-recheck candidates within margin --------
__global__ __launch_bounds__(256) void refine(const float* __restrict__ x,
                                              const float* __restrict__ codes,
                                              float* __restrict__ out){
    const int t = blockIdx.x*8 + (threadIdx.x>>5);
    const int l = threadIdx.x&31;
    const float amin = fminf(g_pacc[t], g_pacc[N_TOK+t]) + MARGIN;
    // preload x row: 16 floats per lane
    float xr[16];
    {
        const float4* xp = (const float4*)(x + (size_t)t*DIM) + l*4;
#pragma unroll
        for (int u=0;u<4;u++){
            float4 v=xp[u];
            xr[u*4]=v.x; xr[u*4+1]=v.y; xr[u*4+2]=v.z; xr[u*4+3]=v.w;
        }
    }
    const float x2=g_x2[t];
    float bv=3.4e38f; int bi=0x7fffffff;
    const uint4* drow = (const uint4*)(g_dist + (size_t)t*N_CODES);
    for (int i=0;i<64;i++){
        uint4 d = drow[i*32+l];
        uint32_t w[4]={d.x,d.y,d.z,d.w};
        uint32_t m8=0;
#pragma unroll
        for (int q=0;q<4;q++){
            __half2 h2=*(__half2*)&w[q];
            if (__low2float(h2)  <= amin) m8|=1u<<(q*2);
            if (__high2float(h2) <= amin) m8|=1u<<(q*2+1);
        }
        uint32_t bal=__ballot_sync(0xffffffffu, m8!=0);
        while (bal){
            int src=__ffs(bal)-1; bal&=bal-1;
            uint32_t mm=__shfl_sync(0xffffffffu,m8,src);
            while (mm){
                int b=__ffs(mm)-1; mm&=mm-1;
                int ci=i*256+src*8+b;
                const float4* cp=(const float4*)(codes+(size_t)ci*DIM)+l*4;
                float s=0.f;
#pragma unroll
                for (int u=0;u<4;u++){
                    float4 v=cp[u];
                    s=fmaf(xr[u*4],v.x,s); s=fmaf(xr[u*4+1],v.y,s);
                    s=fmaf(xr[u*4+2],v.z,s); s=fmaf(xr[u*4+3],v.w,s);
                }
#pragma unroll
                for (int o=16;o>0;o>>=1) s += __shfl_xor_sync(0xffffffffu,s,o);
                float dist = x2 + g_c2[ci] - 2.f*s;
                if (dist<bv || (dist==bv && ci<bi)){ bv=dist; bi=ci; }
            }
        }
    }
    if (l==0) out[t] = (bv<=THRESH) ? (float)bi : -1.0f;
}

extern "C" void kernel_launch(void* const* d_in, const int* in_sizes, int n_in,
                              void* d_out, int out_size){
    const float* x=(const float*)d_in[0];
    const float* codes=(const float*)d_in[1];
    float* out=(float*)d_out;
    cudaFuncSetAttribute(nn_hmma, cudaFuncAttributeMaxDynamicSharedMemorySize, SMEM_DYN);
    prep<<<(N_TOK+N_CODES)/8, 256>>>(x, codes);
    dim3 grid(64,2);
    nn_hmma<<<grid, 512, SMEM_DYN>>>();
    refine<<<N_TOK/8, 256>>>(x, codes, out);
}

// round 7
// speedup vs baseline: 11.1266x; 1.1468x over previous
#include <cuda_runtime.h>
#include <cuda_fp16.h>
#include <cstdint>

#define N_CODES 16384
#define N_TOK   8192
#define DIM     512
#define THRESH  900.0f
#define MARGIN  8.0f
#define CAP     1024
#define BM      128
#define BN      256
#define NKC     8                 // 512/64
#define NTILE   32                // 8192/256
#define NG      (NTILE*NKC)
#define STG     49152u            // A 16KB + B 32KB
#define SMEM_DYN (3u*STG)
#define SWZ(o) ((o) ^ (((o)>>3)&0x70))

__device__ __align__(128) __half g_A[(size_t)N_TOK*DIM];     // x hi
__device__ __align__(128) __half g_B[(size_t)N_CODES*DIM];   // codes hi
__device__ __align__(16) float g_c2[N_CODES];
__device__ __align__(16) float g_x2[N_TOK];
__device__ int g_ccnt[2*N_TOK];
__device__ int g_cand[(size_t)2*N_TOK*CAP];

__device__ __forceinline__ uint32_t s2u(const void* p){
    uint32_t a;
    asm("{ .reg .u64 t; cvta.to.shared.u64 t, %1; cvt.u32.u64 %0, t; }" : "=r"(a) : "l"(p));
    return a;
}
#define CPASYNC16(d,s) asm volatile("cp.async.cg.shared.global [%0], [%1], 16;" :: "r"(d),"l"(s) : "memory")
#define LDSM4(r0,r1,r2,r3,a) asm volatile("ldmatrix.sync.aligned.m8n8.x4.shared.b16 {%0,%1,%2,%3}, [%4];" \
    : "=r"(r0),"=r"(r1),"=r"(r2),"=r"(r3) : "r"(a))
#define LDSM2(r0,r1,a) asm volatile("ldmatrix.sync.aligned.m8n8.x2.shared.b16 {%0,%1}, [%2];" \
    : "=r"(r0),"=r"(r1) : "r"(a))
#define MMA(c,a,b0,b1) asm volatile( \
    "mma.sync.aligned.m16n8k16.row.col.f32.f16.f16.f32 {%0,%1,%2,%3},{%4,%5,%6,%7},{%8,%9},{%0,%1,%2,%3};" \
    : "+f"((c)[0]),"+f"((c)[1]),"+f"((c)[2]),"+f"((c)[3]) \
    : "r"((a)[0]),"r"((a)[1]),"r"((a)[2]),"r"((a)[3]),"r"(b0),"r"(b1))

// ---- prep: fp32 -> fp16 + norms + zero candidate counters -----------------
__global__ __launch_bounds__(256) void prep(const float* __restrict__ x,
                                            const float* __restrict__ codes){
    int flat = blockIdx.x*256+threadIdx.x;
    if (flat < 2*N_TOK) g_ccnt[flat]=0;
    int w=flat>>5, lane=threadIdx.x&31;
    if (w>=N_TOK+N_CODES) return;
    bool isx = w<N_TOK;
    int row = isx ? w : w-N_TOK;
    const float* src = isx ? x+(size_t)row*DIM : codes+(size_t)row*DIM;
    __half* d = isx ? g_A+(size_t)row*DIM : g_B+(size_t)row*DIM;
    float s=0.f;
#pragma unroll
    for (int i=0;i<4;i++){
        float4 v = ((const float4*)src)[lane+32*i];
        int c=(lane+32*i)*4;
        float vv[4]={v.x,v.y,v.z,v.w};
        *(__half2*)(d+c)=__floats2half2_rn(vv[0],vv[1]);
        *(__half2*)(d+c+2)=__floats2half2_rn(vv[2],vv[3]);
#pragma unroll
        for (int u=0;u<4;u++) s=fmaf(vv[u],vv[u],s);
    }
#pragma unroll
    for (int o=16;o>0;o>>=1) s += __shfl_xor_sync(0xffffffffu,s,o);
    if (lane==0){ if (isx) g_x2[row]=s; else g_c2[row]=s; }
}

// ---- approx GEMM + prefix-min candidate selection -------------------------
__device__ __forceinline__ void issue_chunk(uint32_t sd,int tid,int row0,int nbase,int g){
    int it=g/NKC, kc=g%NKC;
    uint32_t st = sd + (uint32_t)(g%3)*STG;
    const __half* pa = g_A + (size_t)row0*DIM + kc*64;
    const __half* pb = g_B + (size_t)(nbase+it*BN)*DIM + kc*64;
#pragma unroll
    for (int i=0;i<2;i++){
        int id=tid+i*512, r=id>>3, c=id&7;
        CPASYNC16(st + SWZ((uint32_t)(r*128+c*16)), pa + (size_t)r*DIM + c*8);
    }
#pragma unroll
    for (int i=0;i<4;i++){
        int id=tid+i*512, r=id>>3, c=id&7;
        CPASYNC16(st + 16384u + SWZ((uint32_t)(r*128+c*16)), pb + (size_t)r*DIM + c*8);
    }
    asm volatile("cp.async.commit_group;" ::: "memory");
}

__global__ __launch_bounds__(512,1) void nn_hmma(){
    extern __shared__ __align__(1024) char dsm[];
    __shared__ __align__(16) float c2s[BN];
    __shared__ float rv[BM][4];
    __shared__ float pfx[BM];
    const uint32_t sd = s2u(dsm);
    const int tid=threadIdx.x, l=tid&31, wid=tid>>5;
    const int wr=wid>>2, wc=wid&3;          // warp 32x64 tile at (wr*32, wc*64)
    const int row0=blockIdx.x*BM;
    const int nbase=blockIdx.y*(N_CODES/2);
    const int half=blockIdx.y;

    float acc[2][8][4];
#pragma unroll
    for (int a=0;a<2;a++)
#pragma unroll
        for (int b=0;b<8;b++)
#pragma unroll
            for (int c=0;c<4;c++) acc[a][b][c]=0.f;
    if (tid<BM) pfx[tid]=3.4e38f;

    issue_chunk(sd,tid,row0,nbase,0);
    issue_chunk(sd,tid,row0,nbase,1);

    for (int g=0; g<NG; g++){
        const int it=g/NKC, kc=g%NKC;
        if (g==NG-1) asm volatile("cp.async.wait_group 0;" ::: "memory");
        else         asm volatile("cp.async.wait_group 1;" ::: "memory");
        __syncthreads();
        if (g+2<NG) issue_chunk(sd,tid,row0,nbase,g+2);
        if (kc==0 && tid<64)
            *(float4*)(c2s+tid*4) = *(const float4*)(g_c2 + nbase + it*BN + tid*4);

        const uint32_t stA = sd + (uint32_t)(g%3)*STG;
        const uint32_t stB = stA + 16384u;
#pragma unroll
        for (int kk=0;kk<4;kk++){
            uint32_t a[2][4];
#pragma unroll
            for (int mt=0;mt<2;mt++){
                uint32_t row=(uint32_t)(wr*32+mt*16+(l&15));
                uint32_t col=(uint32_t)(kk*32+((l>>4)<<4));
                LDSM4(a[mt][0],a[mt][1],a[mt][2],a[mt][3], stA+SWZ(row*128u+col));
            }
#pragma unroll
            for (int nt=0;nt<8;nt++){
                uint32_t brow=(uint32_t)(wc*64+nt*8+(l&7));
                uint32_t bcol=(uint32_t)(kk*32+(((l>>3)&1)<<4));
                uint32_t b0,b1;
                LDSM2(b0,b1, stB+SWZ(brow*128u+bcol));
                MMA(acc[0][nt],a[0],b0,b1);
                MMA(acc[1][nt],a[1],b0,b1);
            }
        }
        if (kc==NKC-1){
            const int tilen = nbase + it*BN;
            // 1) v = c2 - 2*dot in place; per-thread per-row tile min
            float tmin[2][2];
#pragma unroll
            for (int mt=0;mt<2;mt++){ tmin[mt][0]=3.4e38f; tmin[mt][1]=3.4e38f; }
#pragma unroll
            for (int mt=0;mt<2;mt++)
#pragma unroll
                for (int nt=0;nt<8;nt++){
                    int nl = wc*64 + nt*8 + (l&3)*2;
                    float c2v0=c2s[nl], c2v1=c2s[nl+1];
                    float* c = acc[mt][nt];
                    c[0]=fmaf(-2.f,c[0],c2v0); c[1]=fmaf(-2.f,c[1],c2v1);
                    c[2]=fmaf(-2.f,c[2],c2v0); c[3]=fmaf(-2.f,c[3],c2v1);
                    tmin[mt][0]=fminf(tmin[mt][0],fminf(c[0],c[1]));
                    tmin[mt][1]=fminf(tmin[mt][1],fminf(c[2],c[3]));
                }
#pragma unroll
            for (int q=1;q<4;q<<=1)
#pragma unroll
                for (int mt=0;mt<2;mt++){
                    tmin[mt][0]=fminf(tmin[mt][0],__shfl_xor_sync(0xffffffffu,tmin[mt][0],q));
                    tmin[mt][1]=fminf(tmin[mt][1],__shfl_xor_sync(0xffffffffu,tmin[mt][1],q));
                }
            if ((l&3)==0){
                int gq=l>>2;
#pragma unroll
                for (int mt=0;mt<2;mt++){
                    rv[wr*32+mt*16+gq][wc]=tmin[mt][0];
                    rv[wr*32+mt*16+gq+8][wc]=tmin[mt][1];
                }
            }
            __syncthreads();
            // 2) fold tile min into prefix min (tile-inclusive)
            if (tid<BM){
                float p=fminf(fminf(rv[tid][0],rv[tid][1]),fminf(rv[tid][2],rv[tid][3]));
                pfx[tid]=fminf(pfx[tid],p);
            }
            __syncthreads();
            // 3) candidate check + append
#pragma unroll
            for (int mt=0;mt<2;mt++){
                const int m0 = wr*32 + mt*16 + (l>>2);
                const float th0 = pfx[m0]   + MARGIN;
                const float th8 = pfx[m0+8] + MARGIN;
#pragma unroll
                for (int nt=0;nt<8;nt++){
                    int nl = tilen + wc*64 + nt*8 + (l&3)*2;
                    float* c = acc[mt][nt];
                    if (c[0]<=th0){ int gi=half*N_TOK+row0+m0;   int p=atomicAdd(&g_ccnt[gi],1); if(p<CAP) g_cand[(size_t)gi*CAP+p]=nl;   }
                    if (c[1]<=th0){ int gi=half*N_TOK+row0+m0;   int p=atomicAdd(&g_ccnt[gi],1); if(p<CAP) g_cand[(size_t)gi*CAP+p]=nl+1; }
                    if (c[2]<=th8){ int gi=half*N_TOK+row0+m0+8; int p=atomicAdd(&g_ccnt[gi],1); if(p<CAP) g_cand[(size_t)gi*CAP+p]=nl;   }
                    if (c[3]<=th8){ int gi=half*N_TOK+row0+m0+8; int p=atomicAdd(&g_ccnt[gi],1); if(p<CAP) g_cand[(size_t)gi*CAP+p]=nl+1; }
                    c[0]=c[1]=c[2]=c[3]=0.f;
                }
            }
        }
    }
}

// ---- refine: exact fp32 recheck of candidates, warp per token -------------
__global__ __launch_bounds__(256) void refine(const float* __restrict__ x,
                                              const float* __restrict__ codes,
                                              float* __restrict__ out){
    const int t = blockIdx.x*8 + (threadIdx.x>>5);
    const int l = threadIdx.x&31;
    float xr[16];
    {
        const float4* xp = (const float4*)(x + (size_t)t*DIM) + l*4;
#pragma unroll
        for (int u=0;u<4;u++){
            float4 v=xp[u];
            xr[u*4]=v.x; xr[u*4+1]=v.y; xr[u*4+2]=v.z; xr[u*4+3]=v.w;
        }
    }
    const float x2=g_x2[t];
    float bv=3.4e38f; int bi=0x7fffffff;
#pragma unroll
    for (int h=0;h<2;h++){
        const int gi=h*N_TOK+t;
        int cnt=g_ccnt[gi]; if (cnt>CAP) cnt=CAP;
        const int* lst=g_cand+(size_t)gi*CAP;
        for (int j=0;j<cnt;j++){
            int ci=lst[j];
            const float4* cp=(const float4*)(codes+(size_t)ci*DIM)+l*4;
            float s=0.f;
#pragma unroll
            for (int u=0;u<4;u++){
                float4 v=cp[u];
                s=fmaf(xr[u*4],v.x,s); s=fmaf(xr[u*4+1],v.y,s);
                s=fmaf(xr[u*4+2],v.z,s); s=fmaf(xr[u*4+3],v.w,s);
            }
#pragma unroll
            for (int o=16;o>0;o>>=1) s += __shfl_xor_sync(0xffffffffu,s,o);
            float dist = x2 + g_c2[ci] - 2.f*s;
            if (dist<bv || (dist==bv && ci<bi)){ bv=dist; bi=ci; }
        }
    }
    if (l==0) out[t] = (bv<=THRESH) ? (float)bi : -1.0f;
}

extern "C" void kernel_launch(void* const* d_in, const int* in_sizes, int n_in,
                              void* d_out, int out_size){
    const float* x=(const float*)d_in[0];
    const float* codes=(const float*)d_in[1];
    float* out=(float*)d_out;
    cudaFuncSetAttribute(nn_hmma, cudaFuncAttributeMaxDynamicSharedMemorySize, SMEM_DYN);
    prep<<<(N_TOK+N_CODES)/8, 256>>>(x, codes);
    dim3 grid(64,2);
    nn_hmma<<<grid, 512, SMEM_DYN>>>();
    refine<<<N_TOK/8, 256>>>(x, codes, out);
}

// round 9
// speedup vs baseline: 11.4701x; 1.0309x over previous
#include <cuda_runtime.h>
#include <cuda_fp16.h>
#include <cstdint>

#define N_CODES 16384
#define N_TOK   8192
#define DIM     512
#define THRESH  900.0f
#define MARGIN  8.0f
#define CAP     1024
#define BM      128
#define BN      256
#define NKC     8                 // 512/64
#define NTILE   32                // 8192/256
#define NG      (NTILE*NKC)
#define A_BYTES 131072u           // 128 rows x 512 halves, resident
#define STGB    32768u            // one B stage: 256 rows x 128B
#define SMEM_DYN (A_BYTES + 2u*STGB)
#define SWZ(o) ((o) ^ (((o)>>3)&0x70))

__device__ __align__(128) __half g_A[(size_t)N_TOK*DIM];     // x hi
__device__ __align__(128) __half g_B[(size_t)N_CODES*DIM];   // codes hi
__device__ __align__(16) float g_c2[N_CODES];
__device__ __align__(16) float g_x2[N_TOK];
__device__ int g_ccnt[2*N_TOK];
__device__ int g_cand[(size_t)2*N_TOK*CAP];

__device__ __forceinline__ uint32_t s2u(const void* p){
    uint32_t a;
    asm("{ .reg .u64 t; cvta.to.shared.u64 t, %1; cvt.u32.u64 %0, t; }" : "=r"(a) : "l"(p));
    return a;
}
#define CPASYNC16(d,s) asm volatile("cp.async.cg.shared.global [%0], [%1], 16;" :: "r"(d),"l"(s) : "memory")
#define LDSM4(r0,r1,r2,r3,a) asm volatile("ldmatrix.sync.aligned.m8n8.x4.shared.b16 {%0,%1,%2,%3}, [%4];" \
    : "=r"(r0),"=r"(r1),"=r"(r2),"=r"(r3) : "r"(a))
#define MMA(c,a,b0,b1) asm volatile( \
    "mma.sync.aligned.m16n8k16.row.col.f32.f16.f16.f32 {%0,%1,%2,%3},{%4,%5,%6,%7},{%8,%9},{%0,%1,%2,%3};" \
    : "+f"((c)[0]),"+f"((c)[1]),"+f"((c)[2]),"+f"((c)[3]) \
    : "r"((a)[0]),"r"((a)[1]),"r"((a)[2]),"r"((a)[3]),"r"(b0),"r"(b1))

// ---- prep: fp32 -> fp16 + norms + zero candidate counters -----------------
__global__ __launch_bounds__(256) void prep(const float* __restrict__ x,
                                            const float* __restrict__ codes){
    int flat = blockIdx.x*256+threadIdx.x;
    if (flat < 2*N_TOK) g_ccnt[flat]=0;
    int w=flat>>5, lane=threadIdx.x&31;
    if (w>=N_TOK+N_CODES) return;
    bool isx = w<N_TOK;
    int row = isx ? w : w-N_TOK;
    const float* src = isx ? x+(size_t)row*DIM : codes+(size_t)row*DIM;
    __half* d = isx ? g_A+(size_t)row*DIM : g_B+(size_t)row*DIM;
    float s=0.f;
#pragma unroll
    for (int i=0;i<4;i++){
        float4 v = ((const float4*)src)[lane+32*i];
        int c=(lane+32*i)*4;
        float vv[4]={v.x,v.y,v.z,v.w};
        *(__half2*)(d+c)=__floats2half2_rn(vv[0],vv[1]);
        *(__half2*)(d+c+2)=__floats2half2_rn(vv[2],vv[3]);
#pragma unroll
        for (int u=0;u<4;u++) s=fmaf(vv[u],vv[u],s);
    }
#pragma unroll
    for (int o=16;o>0;o>>=1) s += __shfl_xor_sync(0xffffffffu,s,o);
    if (lane==0){ if (isx) g_x2[row]=s; else g_c2[row]=s; }
}

// ---- approx GEMM (A resident, 2-stage B) + prefix-min candidates ----------
__device__ __forceinline__ void issue_B(uint32_t sd,int tid,int nbase,int g){
    int it=g/NKC, kc=g%NKC;
    uint32_t st = sd + A_BYTES + (uint32_t)(g&1)*STGB;
    const __half* pb = g_B + (size_t)(nbase+it*BN)*DIM + kc*64;
#pragma unroll
    for (int i=0;i<4;i++){
        int id=tid+i*512, r=id>>3, c=id&7;
        CPASYNC16(st + SWZ((uint32_t)(r*128+c*16)), pb + (size_t)r*DIM + c*8);
    }
    asm volatile("cp.async.commit_group;" ::: "memory");
}

__global__ __launch_bounds__(512,1) void nn_hmma(){
    extern __shared__ __align__(1024) char dsm[];
    __shared__ __align__(16) float c2s[BN];
    __shared__ float rv[BM][4];
    __shared__ float pfx[BM];
    const uint32_t sd = s2u(dsm);
    const int tid=threadIdx.x, l=tid&31, wid=tid>>5;
    const int wr=wid>>2, wc=wid&3;          // warp 32x64 tile at (wr*32, wc*64)
    const int row0=blockIdx.x*BM;
    const int nbase=blockIdx.y*(N_CODES/2);
    const int half=blockIdx.y;

    float acc[2][8][4];
#pragma unroll
    for (int a=0;a<2;a++)
#pragma unroll
        for (int b=0;b<8;b++)
#pragma unroll
            for (int c=0;c<4;c++) acc[a][b][c]=0.f;
    if (tid<BM) pfx[tid]=3.4e38f;

    // preload A (whole 128x512 block, swizzled per 64-half chunk) + B stage 0
    {
        const __half* pa = g_A + (size_t)row0*DIM;
#pragma unroll
        for (int i=0;i<16;i++){
            int id=tid+i*512;                 // 0..8191 16B units
            int c=id>>10, r=(id>>3)&127, cc=id&7;
            CPASYNC16(sd + (uint32_t)c*16384u + SWZ((uint32_t)(r*128+cc*16)),
                      pa + (size_t)r*DIM + c*64 + cc*8);
        }
        const __half* pb = g_B + (size_t)nbase*DIM;
#pragma unroll
        for (int i=0;i<4;i++){
            int id=tid+i*512, r=id>>3, cc=id&7;
            CPASYNC16(sd + A_BYTES + SWZ((uint32_t)(r*128+cc*16)), pb + (size_t)r*DIM + cc*8);
        }
        asm volatile("cp.async.commit_group;" ::: "memory");
    }
    issue_B(sd,tid,nbase,1);

    for (int g=0; g<NG; g++){
        const int it=g/NKC, kc=g%NKC;
        if (g>=NG-2) asm volatile("cp.async.wait_group 0;" ::: "memory");
        else         asm volatile("cp.async.wait_group 1;" ::: "memory");
        __syncthreads();
        if (kc==0 && tid<64)
            *(float4*)(c2s+tid*4) = *(const float4*)(g_c2 + nbase + it*BN + tid*4);

        const uint32_t stA = sd + (uint32_t)kc*16384u;
        const uint32_t stB = sd + A_BYTES + (uint32_t)(g&1)*STGB;
#pragma unroll
        for (int kk=0;kk<4;kk++){
            uint32_t a[2][4];
#pragma unroll
            for (int mt=0;mt<2;mt++){
                uint32_t row=(uint32_t)(wr*32+mt*16+(l&15));
                uint32_t col=(uint32_t)(kk*32+((l>>4)<<4));
                LDSM4(a[mt][0],a[mt][1],a[mt][2],a[mt][3], stA+SWZ(row*128u+col));
            }
#pragma unroll
            for (int nt0=0;nt0<8;nt0+=2){
                int mi=l>>3;
                uint32_t brow=(uint32_t)(wc*64+nt0*8+((mi>>1)<<3)+(l&7));
                uint32_t bcol=(uint32_t)(kk*32+((mi&1)<<4));
                uint32_t b0,b1,b2,b3;
                LDSM4(b0,b1,b2,b3, stB+SWZ(brow*128u+bcol));
                MMA(acc[0][nt0],a[0],b0,b1);
                MMA(acc[1][nt0],a[1],b0,b1);
                MMA(acc[0][nt0+1],a[0],b2,b3);
                MMA(acc[1][nt0+1],a[1],b2,b3);
            }
        }
        if (kc==NKC-1){
            const int tilen = nbase + it*BN;
            float tmin[2][2];
#pragma unroll
            for (int mt=0;mt<2;mt++){ tmin[mt][0]=3.4e38f; tmin[mt][1]=3.4e38f; }
#pragma unroll
            for (int mt=0;mt<2;mt++)
#pragma unroll
                for (int nt=0;nt<8;nt++){
                    int nl = wc*64 + nt*8 + (l&3)*2;
                    float c2v0=c2s[nl], c2v1=c2s[nl+1];
                    float* c = acc[mt][nt];
                    c[0]=fmaf(-2.f,c[0],c2v0); c[1]=fmaf(-2.f,c[1],c2v1);
                    c[2]=fmaf(-2.f,c[2],c2v0); c[3]=fmaf(-2.f,c[3],c2v1);
                    tmin[mt][0]=fminf(tmin[mt][0],fminf(c[0],c[1]));
                    tmin[mt][1]=fminf(tmin[mt][1],fminf(c[2],c[3]));
                }
#pragma unroll
            for (int q=1;q<4;q<<=1)
#pragma unroll
                for (int mt=0;mt<2;mt++){
                    tmin[mt][0]=fminf(tmin[mt][0],__shfl_xor_sync(0xffffffffu,tmin[mt][0],q));
                    tmin[mt][1]=fminf(tmin[mt][1],__shfl_xor_sync(0xffffffffu,tmin[mt][1],q));
                }
            if ((l&3)==0){
                int gq=l>>2;
#pragma unroll
                for (int mt=0;mt<2;mt++){
                    rv[wr*32+mt*16+gq][wc]=tmin[mt][0];
                    rv[wr*32+mt*16+gq+8][wc]=tmin[mt][1];
                }
            }
            __syncthreads();
            if (tid<BM){
                float p=fminf(fminf(rv[tid][0],rv[tid][1]),fminf(rv[tid][2],rv[tid][3]));
                pfx[tid]=fminf(pfx[tid],p);
            }
            __syncthreads();
#pragma unroll
            for (int mt=0;mt<2;mt++){
                const int m0 = wr*32 + mt*16 + (l>>2);
                const float th0 = pfx[m0]   + MARGIN;
                const float th8 = pfx[m0+8] + MARGIN;
#pragma unroll
                for (int nt=0;nt<8;nt++){
                    int nl = tilen + wc*64 + nt*8 + (l&3)*2;
                    float* c = acc[mt][nt];
                    if (c[0]<=th0){ int gi=half*N_TOK+row0+m0;   int p=atomicAdd(&g_ccnt[gi],1); if(p<CAP) g_cand[(size_t)gi*CAP+p]=nl;   }
                    if (c[1]<=th0){ int gi=half*N_TOK+row0+m0;   int p=atomicAdd(&g_ccnt[gi],1); if(p<CAP) g_cand[(size_t)gi*CAP+p]=nl+1; }
                    if (c[2]<=th8){ int gi=half*N_TOK+row0+m0+8; int p=atomicAdd(&g_ccnt[gi],1); if(p<CAP) g_cand[(size_t)gi*CAP+p]=nl;   }
                    if (c[3]<=th8){ int gi=half*N_TOK+row0+m0+8; int p=atomicAdd(&g_ccnt[gi],1); if(p<CAP) g_cand[(size_t)gi*CAP+p]=nl+1; }
                    c[0]=c[1]=c[2]=c[3]=0.f;
                }
            }
        }
        // 2-stage ring: only prefetch g+2 AFTER every warp is done reading
        // stage g&1 (it is the same physical buffer).
        __syncthreads();
        if (g+2<NG) issue_B(sd,tid,nbase,g+2);
    }
}

// ---- refine: exact fp32 recheck of candidates, warp per token -------------
__global__ __launch_bounds__(256) void refine(const float* __restrict__ x,
                                              const float* __restrict__ codes,
                                              float* __restrict__ out){
    const int t = blockIdx.x*8 + (threadIdx.x>>5);
    const int l = threadIdx.x&31;
    float xr[16];
    {
        const float4* xp = (const float4*)(x + (size_t)t*DIM) + l*4;
#pragma unroll
        for (int u=0;u<4;u++){
            float4 v=xp[u];
            xr[u*4]=v.x; xr[u*4+1]=v.y; xr[u*4+2]=v.z; xr[u*4+3]=v.w;
        }
    }
    const float x2=g_x2[t];
    float bv=3.4e38f; int bi=0x7fffffff;
#pragma unroll
    for (int h=0;h<2;h++){
        const int gi=h*N_TOK+t;
        int cnt=g_ccnt[gi]; if (cnt>CAP) cnt=CAP;
        const int* lst=g_cand+(size_t)gi*CAP;
        for (int j=0;j<cnt;j++){
            int ci=lst[j];
            const float4* cp=(const float4*)(codes+(size_t)ci*DIM)+l*4;
            float s=0.f;
#pragma unroll
            for (int u=0;u<4;u++){
                float4 v=cp[u];
                s=fmaf(xr[u*4],v.x,s); s=fmaf(xr[u*4+1],v.y,s);
                s=fmaf(xr[u*4+2],v.z,s); s=fmaf(xr[u*4+3],v.w,s);
            }
#pragma unroll
            for (int o=16;o>0;o>>=1) s += __shfl_xor_sync(0xffffffffu,s,o);
            float dist = x2 + g_c2[ci] - 2.f*s;
            if (dist<bv || (dist==bv && ci<bi)){ bv=dist; bi=ci; }
        }
    }
    if (l==0) out[t] = (bv<=THRESH) ? (float)bi : -1.0f;
}

extern "C" void kernel_launch(void* const* d_in, const int* in_sizes, int n_in,
                              void* d_out, int out_size){
    const float* x=(const float*)d_in[0];
    const float* codes=(const float*)d_in[1];
    float* out=(float*)d_out;
    cudaFuncSetAttribute(nn_hmma, cudaFuncAttributeMaxDynamicSharedMemorySize, SMEM_DYN);
    prep<<<(N_TOK+N_CODES)/8, 256>>>(x, codes);
    dim3 grid(64,2);
    nn_hmma<<<grid, 512, SMEM_DYN>>>();
    refine<<<N_TOK/8, 256>>>(x, codes, out);
}